// round 6
// baseline (speedup 1.0000x reference)
#include <cuda_runtime.h>
#include <cuda_bf16.h>
#include <cstdint>
#include <cstddef>

#define NN   100000
#define NE   1600000
#define DD   128
#define DOUT 40
#define NLAYERS 3
#define NBLK ((NN + 255) / 256)
#define GTILES ((NN + 127) / 128)
#define NW 7

// ---------------------------------------------------------------------------
// Device scratch. Feature tensors as TWO bf16 planes (hi, lo): x ~= hi+lo.
// ---------------------------------------------------------------------------
__device__ __align__(16) uint16_t g_xhi[(size_t)NN * DD];
__device__ __align__(16) uint16_t g_xlo[(size_t)NN * DD];
__device__ __align__(16) uint16_t g_hhi[(size_t)NN * DD];
__device__ __align__(16) uint16_t g_hlo[(size_t)NN * DD];
__device__ __align__(16) uint16_t g_phi[(size_t)NN * DD];
__device__ __align__(16) uint16_t g_plo[(size_t)NN * DD];
__device__ __align__(16) uint16_t g_whi[(size_t)NW * DD * DD];
__device__ __align__(16) uint16_t g_wlo[(size_t)NW * DD * DD];
__device__ float g_tmp[(size_t)NN * DD];
__device__ int g_deg[NN], g_off[NN], g_cur[NN], g_csr[NE];
__device__ int g_bsum[512], g_boff[512], g_idx64;

// ---------------------------------------------------------------------------
// helpers
// ---------------------------------------------------------------------------
__device__ __forceinline__ uint32_t smem_u32(const void* p) {
    uint32_t a;
    asm("{ .reg .u64 t; cvta.to.shared.u64 t, %1; cvt.u32.u64 %0, t; }"
        : "=r"(a) : "l"(p));
    return a;
}
#define LDSM4(r0, r1, r2, r3, addr) \
    asm volatile("ldmatrix.sync.aligned.m8n8.x4.shared.b16 {%0,%1,%2,%3}, [%4];" \
                 : "=r"(r0), "=r"(r1), "=r"(r2), "=r"(r3) : "r"(addr))
#define MMA16816(c, a, b) \
    asm volatile("mma.sync.aligned.m16n8k16.row.col.f32.bf16.bf16.f32 " \
                 "{%0,%1,%2,%3},{%4,%5,%6,%7},{%8,%9},{%0,%1,%2,%3};" \
                 : "+f"((c)[0]), "+f"((c)[1]), "+f"((c)[2]), "+f"((c)[3]) \
                 : "r"((a)[0]), "r"((a)[1]), "r"((a)[2]), "r"((a)[3]), \
                   "r"((b)[0]), "r"((b)[1]))

__device__ __forceinline__ void split2(float a, float b, uint32_t& hp, uint32_t& lp)
{
    __nv_bfloat16 ha = __float2bfloat16_rn(a), hb = __float2bfloat16_rn(b);
    float ra = a - __bfloat162float(ha), rb = b - __bfloat162float(hb);
    __nv_bfloat16 la = __float2bfloat16_rn(ra), lb = __float2bfloat16_rn(rb);
    hp = (uint32_t)__bfloat16_as_ushort(ha) | ((uint32_t)__bfloat16_as_ushort(hb) << 16);
    lp = (uint32_t)__bfloat16_as_ushort(la) | ((uint32_t)__bfloat16_as_ushort(lb) << 16);
}
__device__ __forceinline__ float2 bf2_to_f2(uint32_t u)
{
    __nv_bfloat162 v = *(__nv_bfloat162*)&u;
    return __bfloat1622float2(v);
}

// ---------------------------------------------------------------------------
// int64 vs int32 edge-index detection
// ---------------------------------------------------------------------------
__global__ void detect_kernel(const int* __restrict__ ei)
{
    if (threadIdx.x == 0) {
        const long long* e64 = (const long long*)ei;
        int ok = 1;
        #pragma unroll 1
        for (int i = 0; i < 16; i++) {
            long long s = e64[i], d = e64[NE + i];
            if (s < 0 || s >= NN || d < 0 || d >= NN) ok = 0;
        }
        g_idx64 = ok;
    }
}
__device__ __forceinline__ int load_src(const int* ei, int e, int w) {
    return w ? (int)((const long long*)ei)[e] : ei[e];
}
__device__ __forceinline__ int load_dst(const int* ei, int e, int w) {
    return w ? (int)((const long long*)ei)[NE + e] : ei[NE + e];
}

// ---------------------------------------------------------------------------
// pack x / W into bf16 planes
// ---------------------------------------------------------------------------
__global__ void pack_x_kernel(const float* __restrict__ x)
{
    int i = blockIdx.x * blockDim.x + threadIdx.x;
    if (i >= NN * DD / 4) return;
    float4 v = ((const float4*)x)[i];
    uint32_t h0, l0, h1, l1;
    split2(v.x, v.y, h0, l0);
    split2(v.z, v.w, h1, l1);
    ((uint2*)g_xhi)[i] = make_uint2(h0, h1);
    ((uint2*)g_xlo)[i] = make_uint2(l0, l1);
}
__global__ void pack_w_kernel(const float* __restrict__ Wl,
                              const float* __restrict__ Wr,
                              const float* __restrict__ Wp1)
{
    int i = blockIdx.x * blockDim.x + threadIdx.x;
    if (i >= NW * DD * DD / 4) return;
    int mat = i >> 12;
    int within = i & 4095;
    const float* src = (mat < 3) ? (Wl + (size_t)mat * DD * DD)
                     : (mat < 6) ? (Wr + (size_t)(mat - 3) * DD * DD)
                                 : Wp1;
    float4 v = ((const float4*)src)[within];
    uint32_t h0, l0, h1, l1;
    split2(v.x, v.y, h0, l0);
    split2(v.z, v.w, h1, l1);
    ((uint2*)g_whi)[i] = make_uint2(h0, h1);
    ((uint2*)g_wlo)[i] = make_uint2(l0, l1);
}

// ---------------------------------------------------------------------------
// CSR build
// ---------------------------------------------------------------------------
__global__ void zero_deg_kernel()
{
    int i = blockIdx.x * blockDim.x + threadIdx.x;
    if (i < NN) g_deg[i] = 0;
}
__global__ void count_kernel(const int* __restrict__ ei)
{
    int e = blockIdx.x * blockDim.x + threadIdx.x;
    if (e < NE) atomicAdd(&g_deg[load_dst(ei, e, g_idx64)], 1);
}
__global__ void scanA_kernel()
{
    __shared__ int s[256];
    int i = blockIdx.x * 256 + threadIdx.x;
    int v = (i < NN) ? g_deg[i] : 0;
    s[threadIdx.x] = v; __syncthreads();
    for (int d = 128; d > 0; d >>= 1) {
        if (threadIdx.x < d) s[threadIdx.x] += s[threadIdx.x + d];
        __syncthreads();
    }
    if (threadIdx.x == 0) g_bsum[blockIdx.x] = s[0];
}
__global__ void scanB_kernel()
{
    __shared__ int s[512];
    int tid = threadIdx.x;
    int v = (tid < NBLK) ? g_bsum[tid] : 0;
    s[tid] = v; __syncthreads();
    for (int d = 1; d < 512; d <<= 1) {
        int t = (tid >= d) ? s[tid - d] : 0;
        __syncthreads();
        s[tid] += t; __syncthreads();
    }
    if (tid < NBLK) g_boff[tid] = s[tid] - v;
}
__global__ void scanC_kernel()
{
    __shared__ int s[256];
    int i = blockIdx.x * 256 + threadIdx.x;
    int v = (i < NN) ? g_deg[i] : 0;
    s[threadIdx.x] = v; __syncthreads();
    for (int d = 1; d < 256; d <<= 1) {
        int t = (threadIdx.x >= d) ? s[threadIdx.x - d] : 0;
        __syncthreads();
        s[threadIdx.x] += t; __syncthreads();
    }
    if (i < NN) {
        int off = g_boff[blockIdx.x] + s[threadIdx.x] - v;
        g_off[i] = off; g_cur[i] = off;
    }
}
__global__ void fill_kernel(const int* __restrict__ ei)
{
    int e = blockIdx.x * blockDim.x + threadIdx.x;
    if (e < NE) {
        int w = g_idx64;
        int src = load_src(ei, e, w);
        int dst = load_dst(ei, e, w);
        g_csr[atomicAdd(&g_cur[dst], 1)] = src;
    }
}

// ---------------------------------------------------------------------------
// Column-blocked gather, pass `half` = cols [64*half, 64*half+64).
// Unroll 8 -> 16 outstanding 128B loads per warp. fp32 accum, re-split.
// ---------------------------------------------------------------------------
__global__ void __launch_bounds__(256)
gather_kernel(const uint16_t* __restrict__ Ahi, const uint16_t* __restrict__ Alo,
              uint16_t* __restrict__ Phi, uint16_t* __restrict__ Plo, int half)
{
    int d    = blockIdx.x * 8 + (threadIdx.x >> 5);
    int lane = threadIdx.x & 31;
    if (d >= NN) return;

    int off = g_off[d], deg = g_deg[d];
    const int colb = half * 64 + lane * 2;
    float a0 = 0.f, a1 = 0.f;

    #define ACC(s) {                                                        \
        uint32_t uh = *(const uint32_t*)(Ahi + (size_t)(s) * DD + colb);    \
        uint32_t ul = *(const uint32_t*)(Alo + (size_t)(s) * DD + colb);    \
        float2 hf = bf2_to_f2(uh), lf = bf2_to_f2(ul);                      \
        a0 += hf.x + lf.x; a1 += hf.y + lf.y; }

    int j = 0;
    for (; j + 8 <= deg; j += 8) {
        int s[8];
        #pragma unroll
        for (int k = 0; k < 8; k++) s[k] = g_csr[off + j + k];
        #pragma unroll
        for (int k = 0; k < 8; k++) ACC(s[k]);
    }
    for (; j < deg; j++) { int s0 = g_csr[off + j]; ACC(s0); }
    #undef ACC

    uint32_t hp, lp;
    split2(a0, a1, hp, lp);
    *(uint32_t*)(Phi + (size_t)d * DD + colb) = hp;
    *(uint32_t*)(Plo + (size_t)d * DD + colb) = lp;
}

// ---------------------------------------------------------------------------
// mma.sync bf16 GEMM, 3xBF16 split, plane inputs, K-blocked.
//   out[n,o] = sum_{k in [kOff,kOff+KLEN)} A[n,k]*W[o,k]  (+bias) (+addin)
//   NORM: row-L2-normalize + ReLU, write planes. else write fp32 outF.
// CTA = 128 rows x 128 cols, 8 warps, warp tile 32x64.
// ---------------------------------------------------------------------------
#define SM_AHI  0
#define SM_ALO  34816
#define SM_WHI  69632
#define SM_WLO  104448
#define SM_BIAS 139264
#define SM_TOTAL 139776

template<int KLEN, bool ADDIN, bool NORM>
__global__ void __launch_bounds__(256, 1)
mma_kernel(const uint16_t* __restrict__ Ahi, const uint16_t* __restrict__ Alo,
           int kOff,
           const uint16_t* __restrict__ Whi, const uint16_t* __restrict__ Wlo,
           const float* __restrict__ b0, const float* __restrict__ b1,
           const float* __restrict__ addin,
           uint16_t* __restrict__ outHi, uint16_t* __restrict__ outLo,
           float* __restrict__ outF)
{
    extern __shared__ char smem[];
    const uint32_t sb = smem_u32(smem);
    const int tid   = threadIdx.x;
    const int lane  = tid & 31;
    const int wid   = tid >> 5;
    const int warpM = wid & 3;
    const int warpN = wid >> 2;
    const int n0    = blockIdx.x * 128;

    float* bsh = (float*)(smem + SM_BIAS);
    if (tid < 128) {
        float b = 0.f;
        if (b0) b += b0[tid];
        if (b1) b += b1[tid];
        bsh[tid] = b;
    }

    float acc[2][8][4];
    #pragma unroll
    for (int mt = 0; mt < 2; mt++)
        #pragma unroll
        for (int nt = 0; nt < 8; nt++)
            #pragma unroll
            for (int r = 0; r < 4; r++)
                acc[mt][nt][r] = 0.f;

    const int mat = lane >> 3, r8 = lane & 7;
    const uint32_t aLane = (uint32_t)((warpM * 32 + (mat & 1) * 8 + r8) * 272
                                      + ((mat >> 1) * 8) * 2);
    const uint32_t bLane = (uint32_t)((warpN * 64 + (mat >> 1) * 8 + r8) * 272
                                      + ((mat & 1) * 8) * 2);

    // ---- pure-copy load of 4 bf16 planes (16B chunks), cols [kOff,kOff+KLEN)
    constexpr int CPR  = KLEN / 8;   // 16B chunks per row
    constexpr int ITER = KLEN / 16;  // (128*CPR)/256
    #pragma unroll
    for (int it = 0; it < ITER; it++) {
        int gi  = tid + it * 256;
        int row = gi / CPR, c = gi % CPR;
        int grow = n0 + row;
        size_t gsrc = (size_t)grow * DD + kOff + c * 8;
        uint32_t dofs = (uint32_t)(row * 272 + c * 16);
        uint4 vh = make_uint4(0,0,0,0), vl = make_uint4(0,0,0,0);
        if (grow < NN) {
            vh = *(const uint4*)(Ahi + gsrc);
            vl = *(const uint4*)(Alo + gsrc);
        }
        *(uint4*)(smem + SM_AHI + dofs) = vh;
        *(uint4*)(smem + SM_ALO + dofs) = vl;
        size_t wsrc = (size_t)row * DD + kOff + c * 8;
        *(uint4*)(smem + SM_WHI + dofs) = *(const uint4*)(Whi + wsrc);
        *(uint4*)(smem + SM_WLO + dofs) = *(const uint4*)(Wlo + wsrc);
    }
    __syncthreads();

    // ---- 3 split products (hi*hi, hi*lo, lo*hi) ----
    #pragma unroll 1
    for (int pr = 0; pr < 3; pr++) {
        const uint32_t aBase = sb + ((pr == 2) ? SM_ALO : SM_AHI) + aLane;
        const uint32_t bBase = sb + ((pr == 1) ? SM_WLO : SM_WHI) + bLane;
        #pragma unroll
        for (int ks = 0; ks < KLEN / 16; ks++) {
            const uint32_t kb = ks * 32;
            uint32_t af[2][4];
            LDSM4(af[0][0], af[0][1], af[0][2], af[0][3], aBase + kb);
            LDSM4(af[1][0], af[1][1], af[1][2], af[1][3], aBase + kb + 16 * 272);
            uint32_t bf[8][2];
            #pragma unroll
            for (int p = 0; p < 4; p++) {
                LDSM4(bf[2*p][0], bf[2*p][1], bf[2*p+1][0], bf[2*p+1][1],
                      bBase + kb + p * 16 * 272);
            }
            #pragma unroll
            for (int mt = 0; mt < 2; mt++)
                #pragma unroll
                for (int nt = 0; nt < 8; nt++)
                    MMA16816(acc[mt][nt], af[mt], bf[nt]);
        }
    }

    // ---- epilogue ----
    __syncthreads();
    float* fbuf = (float*)smem;                 // [128][132] fp32
    {
        int row0 = warpM * 32 + (lane >> 2);
        int col0 = warpN * 64 + (lane & 3) * 2;
        #pragma unroll
        for (int mt = 0; mt < 2; mt++)
            #pragma unroll
            for (int nt = 0; nt < 8; nt++) {
                int r = row0 + mt * 16, c = col0 + nt * 8;
                fbuf[r * 132 + c]           = acc[mt][nt][0];
                fbuf[r * 132 + c + 1]       = acc[mt][nt][1];
                fbuf[(r + 8) * 132 + c]     = acc[mt][nt][2];
                fbuf[(r + 8) * 132 + c + 1] = acc[mt][nt][3];
            }
    }
    __syncthreads();
    {
        int row  = tid >> 1, half = tid & 1;
        int grow = n0 + row;
        if (grow < NN) {
            const float* frow = fbuf + row * 132 + half * 64;
            const float* brow = bsh + half * 64;
            const float* arow = ADDIN
                ? (addin + (size_t)grow * DD + half * 64) : nullptr;
            float inv = 1.0f;
            if (NORM) {
                float ss = 0.f;
                #pragma unroll
                for (int c = 0; c < 64; c++) {
                    float v = frow[c] + brow[c];
                    if (ADDIN) v += arow[c];
                    ss += v * v;
                }
                ss += __shfl_xor_sync(0xffffffffu, ss, 1);
                inv = 1.0f / fmaxf(sqrtf(ss), 1e-12f);
            }
            if (NORM) {
                uint16_t* oh = outHi + (size_t)grow * DD + half * 64;
                uint16_t* ol = outLo + (size_t)grow * DD + half * 64;
                #pragma unroll
                for (int c = 0; c < 64; c += 4) {
                    float4 f = *(const float4*)(frow + c);
                    float4 bv = *(const float4*)(brow + c);
                    f.x += bv.x; f.y += bv.y; f.z += bv.z; f.w += bv.w;
                    if (ADDIN) {
                        float4 av = *(const float4*)(arow + c);
                        f.x += av.x; f.y += av.y; f.z += av.z; f.w += av.w;
                    }
                    f.x = fmaxf(f.x * inv, 0.f);
                    f.y = fmaxf(f.y * inv, 0.f);
                    f.z = fmaxf(f.z * inv, 0.f);
                    f.w = fmaxf(f.w * inv, 0.f);
                    uint32_t h0, l0, h1, l1;
                    split2(f.x, f.y, h0, l0);
                    split2(f.z, f.w, h1, l1);
                    *(uint2*)(oh + c) = make_uint2(h0, h1);
                    *(uint2*)(ol + c) = make_uint2(l0, l1);
                }
            } else {
                float* orow = outF + (size_t)grow * DD + half * 64;
                #pragma unroll
                for (int c = 0; c < 64; c += 4) {
                    float4 f = *(const float4*)(frow + c);
                    float4 bv = *(const float4*)(brow + c);
                    f.x += bv.x; f.y += bv.y; f.z += bv.z; f.w += bv.w;
                    if (ADDIN) {
                        float4 av = *(const float4*)(arow + c);
                        f.x += av.x; f.y += av.y; f.z += av.z; f.w += av.w;
                    }
                    *(float4*)(orow + c) = f;
                }
            }
        }
    }
}

// ---------------------------------------------------------------------------
// post2 + log_softmax (fp32)
// ---------------------------------------------------------------------------
__global__ void __launch_bounds__(256)
post2_kernel(const float* __restrict__ h, const float* __restrict__ W,
             const float* __restrict__ b, float* __restrict__ out)
{
    __shared__ float Ws[DOUT * DD];
    __shared__ float bs[DOUT];
    const int tid = threadIdx.x;
    for (int i = tid; i < DOUT * DD; i += blockDim.x) Ws[i] = W[i];
    if (tid < DOUT) bs[tid] = b[tid];
    __syncthreads();

    int n = blockIdx.x * blockDim.x + tid;
    if (n >= NN) return;

    float acc[DOUT];
    #pragma unroll
    for (int o = 0; o < DOUT; o++) acc[o] = bs[o];

    const float4* row = (const float4*)(h + (size_t)n * DD);
    #pragma unroll 1
    for (int kq = 0; kq < DD / 4; kq++) {
        float4 x = row[kq];
        #pragma unroll
        for (int o = 0; o < DOUT; o++) {
            const float* wr = &Ws[o * DD + kq * 4];
            acc[o] = fmaf(x.x, wr[0], acc[o]);
            acc[o] = fmaf(x.y, wr[1], acc[o]);
            acc[o] = fmaf(x.z, wr[2], acc[o]);
            acc[o] = fmaf(x.w, wr[3], acc[o]);
        }
    }
    float m = acc[0];
    #pragma unroll
    for (int o = 1; o < DOUT; o++) m = fmaxf(m, acc[o]);
    float s = 0.f;
    #pragma unroll
    for (int o = 0; o < DOUT; o++) s += expf(acc[o] - m);
    float ls = logf(s);
    #pragma unroll
    for (int o = 0; o < DOUT; o++)
        out[(size_t)n * DOUT + o] = acc[o] - m - ls;
}

// ---------------------------------------------------------------------------
// Static stream/event resources
// ---------------------------------------------------------------------------
struct GpuRes {
    cudaStream_t s2;
    cudaEvent_t evF, evCSR, evPack, evP0, evP1, evH;
    GpuRes() {
        cudaStreamCreateWithFlags(&s2, cudaStreamNonBlocking);
        cudaEventCreateWithFlags(&evF,   cudaEventDisableTiming);
        cudaEventCreateWithFlags(&evCSR, cudaEventDisableTiming);
        cudaEventCreateWithFlags(&evPack, cudaEventDisableTiming);
        cudaEventCreateWithFlags(&evP0,  cudaEventDisableTiming);
        cudaEventCreateWithFlags(&evP1,  cudaEventDisableTiming);
        cudaEventCreateWithFlags(&evH,   cudaEventDisableTiming);
    }
};
static GpuRes g_res;

// ---------------------------------------------------------------------------
// Launcher. Per layer l:
//   s2: gather pass0 (cols 0:64)   -> evP0 ; gather pass1 (cols 64:128) -> evP1
//   s0: gemmL  = h@Wl + (bl+br)                -> tmp   (overlaps pass0)
//   s0: [evP0] gemmR1: tmp += prop[:, :64]@Wr[:, :64]   (overlaps pass1)
//   s0: [evP1] gemmR2: tmp + prop[:,64:]@Wr[:,64:] -> norm+relu -> h planes
// ---------------------------------------------------------------------------
extern "C" void kernel_launch(void* const* d_in, const int* in_sizes, int n_in,
                              void* d_out, int out_size)
{
    const float* x   = (const float*)d_in[0];
    const int*   ei  = (const int*)  d_in[1];
    const float* Wl  = (const float*)d_in[2];
    const float* bl  = (const float*)d_in[3];
    const float* Wr  = (const float*)d_in[4];
    const float* br  = (const float*)d_in[5];
    const float* Wp1 = (const float*)d_in[6];
    const float* bp1 = (const float*)d_in[7];
    const float* Wp2 = (const float*)d_in[8];
    const float* bp2 = (const float*)d_in[9];
    float* out = (float*)d_out;

    cudaFuncSetAttribute(mma_kernel<128, false, false>,
                         cudaFuncAttributeMaxDynamicSharedMemorySize, SM_TOTAL);
    cudaFuncSetAttribute(mma_kernel<64, true, false>,
                         cudaFuncAttributeMaxDynamicSharedMemorySize, SM_TOTAL);
    cudaFuncSetAttribute(mma_kernel<64, true, true>,
                         cudaFuncAttributeMaxDynamicSharedMemorySize, SM_TOTAL);

    uint16_t *xhi, *xlo, *hhi, *hlo, *phi, *plo, *whi, *wlo;
    float* tmp;
    cudaGetSymbolAddress((void**)&xhi, g_xhi);
    cudaGetSymbolAddress((void**)&xlo, g_xlo);
    cudaGetSymbolAddress((void**)&hhi, g_hhi);
    cudaGetSymbolAddress((void**)&hlo, g_hlo);
    cudaGetSymbolAddress((void**)&phi, g_phi);
    cudaGetSymbolAddress((void**)&plo, g_plo);
    cudaGetSymbolAddress((void**)&whi, g_whi);
    cudaGetSymbolAddress((void**)&wlo, g_wlo);
    cudaGetSymbolAddress((void**)&tmp, g_tmp);

    cudaStream_t s0 = 0, s2 = g_res.s2;

    detect_kernel<<<1, 1, 0, s0>>>(ei);
    cudaEventRecord(g_res.evF, s0);
    cudaStreamWaitEvent(s2, g_res.evF, 0);

    // CSR build on s2; packs on s0 (overlapped)
    zero_deg_kernel<<<NBLK, 256, 0, s2>>>();
    count_kernel<<<(NE + 255) / 256, 256, 0, s2>>>(ei);
    scanA_kernel<<<NBLK, 256, 0, s2>>>();
    scanB_kernel<<<1, 512, 0, s2>>>();
    scanC_kernel<<<NBLK, 256, 0, s2>>>();
    fill_kernel<<<(NE + 255) / 256, 256, 0, s2>>>(ei);

    pack_x_kernel<<<(NN * DD / 4 + 255) / 256, 256, 0, s0>>>(x);
    pack_w_kernel<<<(NW * DD * DD / 4 + 255) / 256, 256, 0, s0>>>(Wl, Wr, Wp1);
    cudaEventRecord(g_res.evPack, s0);
    cudaStreamWaitEvent(s2, g_res.evPack, 0);   // gathers read x planes

    const int GGB = (NN + 7) / 8;
    const size_t WSZ = (size_t)DD * DD;
    for (int l = 0; l < NLAYERS; l++) {
        const uint16_t* ahi = (l == 0) ? xhi : hhi;
        const uint16_t* alo = (l == 0) ? xlo : hlo;
        const uint16_t* wrh = whi + (size_t)(3 + l) * WSZ;
        const uint16_t* wrl = wlo + (size_t)(3 + l) * WSZ;

        if (l > 0) cudaStreamWaitEvent(s2, g_res.evH, 0);
        gather_kernel<<<GGB, 256, 0, s2>>>(ahi, alo, phi, plo, 0);
        cudaEventRecord(g_res.evP0, s2);
        gather_kernel<<<GGB, 256, 0, s2>>>(ahi, alo, phi, plo, 1);
        cudaEventRecord(g_res.evP1, s2);

        // gemmL (overlaps gather pass0): tmp = h@Wl + (bl+br)
        mma_kernel<128, false, false><<<GTILES, 256, SM_TOTAL, s0>>>(
            ahi, alo, 0,
            whi + (size_t)l * WSZ, wlo + (size_t)l * WSZ,
            bl + (size_t)l * DD, br + (size_t)l * DD,
            nullptr, nullptr, nullptr, tmp);

        // gemmR1 (overlaps gather pass1): tmp += prop[:, :64]@Wr[:, :64]
        cudaStreamWaitEvent(s0, g_res.evP0, 0);
        mma_kernel<64, true, false><<<GTILES, 256, SM_TOTAL, s0>>>(
            phi, plo, 0, wrh, wrl,
            nullptr, nullptr, tmp, nullptr, nullptr, tmp);

        // gemmR2: h = normrelu(tmp + prop[:,64:]@Wr[:,64:])
        cudaStreamWaitEvent(s0, g_res.evP1, 0);
        mma_kernel<64, true, true><<<GTILES, 256, SM_TOTAL, s0>>>(
            phi, plo, 64, wrh, wrl,
            nullptr, nullptr, tmp, hhi, hlo, nullptr);
        cudaEventRecord(g_res.evH, s0);
    }

    // post1 -> tmp, post2 + log_softmax -> out
    mma_kernel<128, false, false><<<GTILES, 256, SM_TOTAL, s0>>>(
        hhi, hlo, 0,
        whi + (size_t)6 * WSZ, wlo + (size_t)6 * WSZ,
        bp1, nullptr, nullptr, nullptr, nullptr, tmp);
    post2_kernel<<<NBLK, 256, 0, s0>>>(tmp, Wp2, bp2, out);
}

// round 7
// speedup vs baseline: 2.9040x; 2.9040x over previous
#include <cuda_runtime.h>
#include <cuda_bf16.h>
#include <cstdint>
#include <cstddef>

#define NN   100000
#define NE   1600000
#define DD   128
#define DOUT 40
#define NLAYERS 3
#define NBLK ((NN + 255) / 256)
#define GTILES ((NN + 127) / 128)
#define NW 6   // Wl0..2, Wr0..2 (post weights are algebraically combined)

// ---------------------------------------------------------------------------
// Device scratch. Features stored as SINGLE bf16 plane (metric margin: R5
// measured 5.5e-8 with 2^-18 elementwise error -> linear extrapolation puts
// bf16 (2^-10..2^-9) at ~2e-5, 30x under the 1e-3 threshold).
// ---------------------------------------------------------------------------
__device__ __align__(16) uint16_t g_xb[(size_t)NN * DD];
__device__ __align__(16) uint16_t g_hb[(size_t)NN * DD];
__device__ __align__(16) uint16_t g_pb[(size_t)NN * DD];
__device__ __align__(16) uint16_t g_wb[(size_t)NW * DD * DD];
__device__ float g_wpost[DOUT * DD];
__device__ float g_bpost[DOUT];
__device__ int g_deg[NN], g_off[NN], g_cur[NN], g_csr[NE];
__device__ int g_bsum[512], g_boff[512], g_idx64;

// ---------------------------------------------------------------------------
// helpers
// ---------------------------------------------------------------------------
__device__ __forceinline__ uint32_t smem_u32(const void* p) {
    uint32_t a;
    asm("{ .reg .u64 t; cvta.to.shared.u64 t, %1; cvt.u32.u64 %0, t; }"
        : "=r"(a) : "l"(p));
    return a;
}
#define LDSM4(r0, r1, r2, r3, addr) \
    asm volatile("ldmatrix.sync.aligned.m8n8.x4.shared.b16 {%0,%1,%2,%3}, [%4];" \
                 : "=r"(r0), "=r"(r1), "=r"(r2), "=r"(r3) : "r"(addr))
#define MMA16816(c, a, b) \
    asm volatile("mma.sync.aligned.m16n8k16.row.col.f32.bf16.bf16.f32 " \
                 "{%0,%1,%2,%3},{%4,%5,%6,%7},{%8,%9},{%0,%1,%2,%3};" \
                 : "+f"((c)[0]), "+f"((c)[1]), "+f"((c)[2]), "+f"((c)[3]) \
                 : "r"((a)[0]), "r"((a)[1]), "r"((a)[2]), "r"((a)[3]), \
                   "r"((b)[0]), "r"((b)[1]))

__device__ __forceinline__ float2 bf2_to_f2(uint32_t u)
{
    __nv_bfloat162 v = *(__nv_bfloat162*)&u;
    return __bfloat1622float2(v);
}
__device__ __forceinline__ uint32_t f2_to_bf2(float a, float b)
{
    __nv_bfloat162 v = __floats2bfloat162_rn(a, b);   // v.x = a, v.y = b
    return *(uint32_t*)&v;
}

// ---------------------------------------------------------------------------
// int64 vs int32 edge-index detection
// ---------------------------------------------------------------------------
__global__ void detect_kernel(const int* __restrict__ ei)
{
    if (threadIdx.x == 0) {
        const long long* e64 = (const long long*)ei;
        int ok = 1;
        #pragma unroll 1
        for (int i = 0; i < 16; i++) {
            long long s = e64[i], d = e64[NE + i];
            if (s < 0 || s >= NN || d < 0 || d >= NN) ok = 0;
        }
        g_idx64 = ok;
    }
}
__device__ __forceinline__ int load_src(const int* ei, int e, int w) {
    return w ? (int)((const long long*)ei)[e] : ei[e];
}
__device__ __forceinline__ int load_dst(const int* ei, int e, int w) {
    return w ? (int)((const long long*)ei)[NE + e] : ei[NE + e];
}

// ---------------------------------------------------------------------------
// pack x / W into single bf16 planes
// ---------------------------------------------------------------------------
__global__ void pack_x_kernel(const float* __restrict__ x)
{
    int i = blockIdx.x * blockDim.x + threadIdx.x;     // float4 index
    if (i >= NN * DD / 4) return;
    float4 v = ((const float4*)x)[i];
    ((uint2*)g_xb)[i] = make_uint2(f2_to_bf2(v.x, v.y), f2_to_bf2(v.z, v.w));
}
__global__ void pack_w_kernel(const float* __restrict__ Wl,
                              const float* __restrict__ Wr)
{
    int i = blockIdx.x * blockDim.x + threadIdx.x;
    if (i >= NW * DD * DD / 4) return;
    int mat = i >> 12;                                  // 4096 float4 / matrix
    int within = i & 4095;
    const float* src = (mat < 3) ? (Wl + (size_t)mat * DD * DD)
                                 : (Wr + (size_t)(mat - 3) * DD * DD);
    float4 v = ((const float4*)src)[within];
    ((uint2*)g_wb)[i] = make_uint2(f2_to_bf2(v.x, v.y), f2_to_bf2(v.z, v.w));
}

// ---------------------------------------------------------------------------
// Combine post weights: W' = Wp2 @ Wp1  [DOUT, DD], b' = Wp2 @ bp1 + bp2
// (post1 layer eliminated algebraically; fp32 exact association change only)
// ---------------------------------------------------------------------------
__global__ void combine_kernel(const float* __restrict__ Wp1,
                               const float* __restrict__ bp1,
                               const float* __restrict__ Wp2,
                               const float* __restrict__ bp2)
{
    int o = blockIdx.x;       // 0..DOUT-1
    int k = threadIdx.x;      // 0..DD-1
    float s = 0.f;
    #pragma unroll 4
    for (int j = 0; j < DD; j++)
        s += Wp2[o * DD + j] * Wp1[(size_t)j * DD + k];
    g_wpost[o * DD + k] = s;
    if (k == 0) {
        float b = bp2[o];
        for (int j = 0; j < DD; j++)
            b += Wp2[o * DD + j] * bp1[j];
        g_bpost[o] = b;
    }
}

// ---------------------------------------------------------------------------
// CSR build (R2-proven)
// ---------------------------------------------------------------------------
__global__ void zero_deg_kernel()
{
    int i = blockIdx.x * blockDim.x + threadIdx.x;
    if (i < NN) g_deg[i] = 0;
}
__global__ void count_kernel(const int* __restrict__ ei)
{
    int e = blockIdx.x * blockDim.x + threadIdx.x;
    if (e < NE) atomicAdd(&g_deg[load_dst(ei, e, g_idx64)], 1);
}
__global__ void scanA_kernel()
{
    __shared__ int s[256];
    int i = blockIdx.x * 256 + threadIdx.x;
    int v = (i < NN) ? g_deg[i] : 0;
    s[threadIdx.x] = v; __syncthreads();
    for (int d = 128; d > 0; d >>= 1) {
        if (threadIdx.x < d) s[threadIdx.x] += s[threadIdx.x + d];
        __syncthreads();
    }
    if (threadIdx.x == 0) g_bsum[blockIdx.x] = s[0];
}
__global__ void scanB_kernel()
{
    __shared__ int s[512];
    int tid = threadIdx.x;
    int v = (tid < NBLK) ? g_bsum[tid] : 0;
    s[tid] = v; __syncthreads();
    for (int d = 1; d < 512; d <<= 1) {
        int t = (tid >= d) ? s[tid - d] : 0;
        __syncthreads();
        s[tid] += t; __syncthreads();
    }
    if (tid < NBLK) g_boff[tid] = s[tid] - v;
}
__global__ void scanC_kernel()
{
    __shared__ int s[256];
    int i = blockIdx.x * 256 + threadIdx.x;
    int v = (i < NN) ? g_deg[i] : 0;
    s[threadIdx.x] = v; __syncthreads();
    for (int d = 1; d < 256; d <<= 1) {
        int t = (threadIdx.x >= d) ? s[threadIdx.x - d] : 0;
        __syncthreads();
        s[threadIdx.x] += t; __syncthreads();
    }
    if (i < NN) {
        int off = g_boff[blockIdx.x] + s[threadIdx.x] - v;
        g_off[i] = off; g_cur[i] = off;
    }
}
__global__ void fill_kernel(const int* __restrict__ ei)
{
    int e = blockIdx.x * blockDim.x + threadIdx.x;
    if (e < NE) {
        int w = g_idx64;
        int src = load_src(ei, e, w);
        int dst = load_dst(ei, e, w);
        g_csr[atomicAdd(&g_cur[dst], 1)] = src;
    }
}

// ---------------------------------------------------------------------------
// Gather (single pass, bf16 rows): prop[d] = sum_{src in N(d)} h[src]
// Warp per node; lane owns 4 cols (8B). 256B/edge, fp32 accumulation.
// Working set (h 25.6MB + prop 25.6MB + csr 6.4MB) is fully L2-resident.
// ---------------------------------------------------------------------------
__global__ void __launch_bounds__(256)
gather_kernel(const uint16_t* __restrict__ A, uint16_t* __restrict__ P)
{
    int d    = blockIdx.x * 8 + (threadIdx.x >> 5);
    int lane = threadIdx.x & 31;
    if (d >= NN) return;

    int off = g_off[d], deg = g_deg[d];
    float a0 = 0.f, a1 = 0.f, a2 = 0.f, a3 = 0.f;

    #define ACC(s) {                                                  \
        uint2 v = *(const uint2*)(A + (size_t)(s) * DD + lane * 4);   \
        float2 f0 = bf2_to_f2(v.x), f1 = bf2_to_f2(v.y);              \
        a0 += f0.x; a1 += f0.y; a2 += f1.x; a3 += f1.y; }

    int j = 0;
    for (; j + 8 <= deg; j += 8) {
        int s[8];
        #pragma unroll
        for (int k = 0; k < 8; k++) s[k] = g_csr[off + j + k];
        #pragma unroll
        for (int k = 0; k < 8; k++) ACC(s[k]);
    }
    for (; j < deg; j++) { int s0 = g_csr[off + j]; ACC(s0); }
    #undef ACC

    *(uint2*)(P + (size_t)d * DD + lane * 4) =
        make_uint2(f2_to_bf2(a0, a1), f2_to_bf2(a2, a3));
}

// ---------------------------------------------------------------------------
// Fused layer GEMM (mma.sync bf16, single product, fp32 accum):
//   D = A0@W0^T + A1@W1^T + (b0+b1); row-L2-normalize + ReLU -> bf16 out.
// CTA = 128x128, 8 warps (warp tile 32x64), 2 CTAs/SM (70KB smem).
// smem rows stride 272B (rotated bank groups, ldmatrix conflict-free).
// ---------------------------------------------------------------------------
#define SM_A    0
#define SM_W    34816
#define SM_BIAS 69632
#define SM_TOTAL 70144

__global__ void __launch_bounds__(256, 2)
mma_kernel(const uint16_t* __restrict__ A0, const uint16_t* __restrict__ A1,
           const uint16_t* __restrict__ W0, const uint16_t* __restrict__ W1,
           const float* __restrict__ b0, const float* __restrict__ b1,
           uint16_t* __restrict__ outB)
{
    extern __shared__ char smem[];
    const uint32_t sb = smem_u32(smem);
    const int tid   = threadIdx.x;
    const int lane  = tid & 31;
    const int wid   = tid >> 5;
    const int warpM = wid & 3;
    const int warpN = wid >> 2;
    const int n0    = blockIdx.x * 128;

    float* bsh = (float*)(smem + SM_BIAS);
    if (tid < 128) bsh[tid] = b0[tid] + b1[tid];

    float acc[2][8][4];
    #pragma unroll
    for (int mt = 0; mt < 2; mt++)
        #pragma unroll
        for (int nt = 0; nt < 8; nt++)
            #pragma unroll
            for (int r = 0; r < 4; r++)
                acc[mt][nt][r] = 0.f;

    const int mat = lane >> 3, r8 = lane & 7;
    const uint32_t aLane = (uint32_t)((warpM * 32 + (mat & 1) * 8 + r8) * 272
                                      + ((mat >> 1) * 8) * 2);
    const uint32_t bLane = (uint32_t)((warpN * 64 + (mat >> 1) * 8 + r8) * 272
                                      + ((mat & 1) * 8) * 2);

    #pragma unroll 1
    for (int ph = 0; ph < 2; ph++) {
        const uint16_t* A = ph ? A1 : A0;
        const uint16_t* W = ph ? W1 : W0;

        __syncthreads();
        // load A (guarded) and W planes: 16B chunks, 8 iters covers both
        #pragma unroll
        for (int it = 0; it < 8; it++) {
            int gi  = tid + it * 256;        // 0..2047
            int row = gi >> 4, c = gi & 15;
            int grow = n0 + row;
            uint32_t dofs = (uint32_t)(row * 272 + c * 16);
            uint4 va = make_uint4(0, 0, 0, 0);
            if (grow < NN)
                va = *(const uint4*)(A + (size_t)grow * DD + c * 8);
            *(uint4*)(smem + SM_A + dofs) = va;
            *(uint4*)(smem + SM_W + dofs) =
                *(const uint4*)(W + (size_t)row * DD + c * 8);
        }
        __syncthreads();

        #pragma unroll
        for (int ks = 0; ks < 8; ks++) {
            const uint32_t kb = ks * 32;
            uint32_t af[2][4];
            LDSM4(af[0][0], af[0][1], af[0][2], af[0][3], sb + SM_A + aLane + kb);
            LDSM4(af[1][0], af[1][1], af[1][2], af[1][3],
                  sb + SM_A + aLane + kb + 16 * 272);
            uint32_t bf[8][2];
            #pragma unroll
            for (int p = 0; p < 4; p++) {
                LDSM4(bf[2*p][0], bf[2*p][1], bf[2*p+1][0], bf[2*p+1][1],
                      sb + SM_W + bLane + kb + p * 16 * 272);
            }
            #pragma unroll
            for (int mt = 0; mt < 2; mt++)
                #pragma unroll
                for (int nt = 0; nt < 8; nt++)
                    MMA16816(acc[mt][nt], af[mt], bf[nt]);
        }
    }

    // ---- epilogue: stage fp32 acc in smem (67.6KB fits in A+W region) ----
    __syncthreads();
    float* fbuf = (float*)smem;                 // [128][132]
    {
        int row0 = warpM * 32 + (lane >> 2);
        int col0 = warpN * 64 + (lane & 3) * 2;
        #pragma unroll
        for (int mt = 0; mt < 2; mt++)
            #pragma unroll
            for (int nt = 0; nt < 8; nt++) {
                int r = row0 + mt * 16, c = col0 + nt * 8;
                fbuf[r * 132 + c]           = acc[mt][nt][0];
                fbuf[r * 132 + c + 1]       = acc[mt][nt][1];
                fbuf[(r + 8) * 132 + c]     = acc[mt][nt][2];
                fbuf[(r + 8) * 132 + c + 1] = acc[mt][nt][3];
            }
    }
    __syncthreads();
    {
        int row  = tid >> 1, half = tid & 1;
        int grow = n0 + row;
        if (grow < NN) {
            const float* frow = fbuf + row * 132 + half * 64;
            const float* brow = bsh + half * 64;
            float ss = 0.f;
            #pragma unroll
            for (int c = 0; c < 64; c++) {
                float v = frow[c] + brow[c];
                ss += v * v;
            }
            ss += __shfl_xor_sync(0xffffffffu, ss, 1);
            float inv = 1.0f / fmaxf(sqrtf(ss), 1e-12f);

            uint16_t* orow = outB + (size_t)grow * DD + half * 64;
            #pragma unroll
            for (int c = 0; c < 64; c += 4) {
                float4 f = *(const float4*)(frow + c);
                float4 bv = *(const float4*)(brow + c);
                f.x = fmaxf((f.x + bv.x) * inv, 0.f);
                f.y = fmaxf((f.y + bv.y) * inv, 0.f);
                f.z = fmaxf((f.z + bv.z) * inv, 0.f);
                f.w = fmaxf((f.w + bv.w) * inv, 0.f);
                *(uint2*)(orow + c) = make_uint2(f2_to_bf2(f.x, f.y),
                                                 f2_to_bf2(f.z, f.w));
            }
        }
    }
}

// ---------------------------------------------------------------------------
// Final: out = log_softmax(h @ W'^T + b'), h in bf16, W' fp32 in smem.
// ---------------------------------------------------------------------------
__global__ void __launch_bounds__(256)
final_kernel(const uint16_t* __restrict__ hb, float* __restrict__ out)
{
    __shared__ float Ws[DOUT * DD];
    __shared__ float bs[DOUT];
    const int tid = threadIdx.x;
    for (int i = tid; i < DOUT * DD; i += blockDim.x) Ws[i] = g_wpost[i];
    if (tid < DOUT) bs[tid] = g_bpost[tid];
    __syncthreads();

    int n = blockIdx.x * blockDim.x + tid;
    if (n >= NN) return;

    float acc[DOUT];
    #pragma unroll
    for (int o = 0; o < DOUT; o++) acc[o] = bs[o];

    const uint2* hr = (const uint2*)(hb + (size_t)n * DD);
    #pragma unroll 1
    for (int kq = 0; kq < DD / 4; kq++) {
        uint2 v = hr[kq];
        float2 f0 = bf2_to_f2(v.x), f1 = bf2_to_f2(v.y);
        #pragma unroll
        for (int o = 0; o < DOUT; o++) {
            const float* wr = &Ws[o * DD + kq * 4];
            acc[o] = fmaf(f0.x, wr[0], acc[o]);
            acc[o] = fmaf(f0.y, wr[1], acc[o]);
            acc[o] = fmaf(f1.x, wr[2], acc[o]);
            acc[o] = fmaf(f1.y, wr[3], acc[o]);
        }
    }
    float m = acc[0];
    #pragma unroll
    for (int o = 1; o < DOUT; o++) m = fmaxf(m, acc[o]);
    float s = 0.f;
    #pragma unroll
    for (int o = 0; o < DOUT; o++) s += expf(acc[o] - m);
    float ls = logf(s);
    #pragma unroll
    for (int o = 0; o < DOUT; o++)
        out[(size_t)n * DOUT + o] = acc[o] - m - ls;
}

// ---------------------------------------------------------------------------
// Static stream/event resources
// ---------------------------------------------------------------------------
struct GpuRes {
    cudaStream_t s2;
    cudaEvent_t evF, evAux;
    GpuRes() {
        cudaStreamCreateWithFlags(&s2, cudaStreamNonBlocking);
        cudaEventCreateWithFlags(&evF,   cudaEventDisableTiming);
        cudaEventCreateWithFlags(&evAux, cudaEventDisableTiming);
    }
};
static GpuRes g_res;

// ---------------------------------------------------------------------------
// Launcher. Setup: CSR + post-weight combine on s2, packs on s0 (overlap).
// Main: strictly serial gather -> mma per layer (gather owns the L2).
// ---------------------------------------------------------------------------
extern "C" void kernel_launch(void* const* d_in, const int* in_sizes, int n_in,
                              void* d_out, int out_size)
{
    const float* x   = (const float*)d_in[0];
    const int*   ei  = (const int*)  d_in[1];
    const float* Wl  = (const float*)d_in[2];
    const float* bl  = (const float*)d_in[3];
    const float* Wr  = (const float*)d_in[4];
    const float* br  = (const float*)d_in[5];
    const float* Wp1 = (const float*)d_in[6];
    const float* bp1 = (const float*)d_in[7];
    const float* Wp2 = (const float*)d_in[8];
    const float* bp2 = (const float*)d_in[9];
    float* out = (float*)d_out;

    cudaFuncSetAttribute(mma_kernel,
                         cudaFuncAttributeMaxDynamicSharedMemorySize, SM_TOTAL);

    uint16_t *xb, *hb, *pb, *wb;
    cudaGetSymbolAddress((void**)&xb, g_xb);
    cudaGetSymbolAddress((void**)&hb, g_hb);
    cudaGetSymbolAddress((void**)&pb, g_pb);
    cudaGetSymbolAddress((void**)&wb, g_wb);

    cudaStream_t s0 = 0, s2 = g_res.s2;

    detect_kernel<<<1, 1, 0, s0>>>(ei);
    cudaEventRecord(g_res.evF, s0);
    cudaStreamWaitEvent(s2, g_res.evF, 0);

    // s2: CSR build + post-weight combine
    zero_deg_kernel<<<NBLK, 256, 0, s2>>>();
    count_kernel<<<(NE + 255) / 256, 256, 0, s2>>>(ei);
    scanA_kernel<<<NBLK, 256, 0, s2>>>();
    scanB_kernel<<<1, 512, 0, s2>>>();
    scanC_kernel<<<NBLK, 256, 0, s2>>>();
    fill_kernel<<<(NE + 255) / 256, 256, 0, s2>>>(ei);
    combine_kernel<<<DOUT, DD, 0, s2>>>(Wp1, bp1, Wp2, bp2);
    cudaEventRecord(g_res.evAux, s2);

    // s0: packs (overlap CSR)
    pack_x_kernel<<<(NN * DD / 4 + 255) / 256, 256, 0, s0>>>(x);
    pack_w_kernel<<<(NW * DD * DD / 4 + 255) / 256, 256, 0, s0>>>(Wl, Wr);
    cudaStreamWaitEvent(s0, g_res.evAux, 0);

    const int GGB = (NN + 7) / 8;
    const size_t WSZ = (size_t)DD * DD;
    for (int l = 0; l < NLAYERS; l++) {
        const uint16_t* ab = (l == 0) ? xb : hb;
        gather_kernel<<<GGB, 256, 0, s0>>>(ab, pb);
        mma_kernel<<<GTILES, 256, SM_TOTAL, s0>>>(
            ab, pb,
            wb + (size_t)l * WSZ, wb + (size_t)(3 + l) * WSZ,
            bl + (size_t)l * DD, br + (size_t)l * DD,
            hb);
    }

    final_kernel<<<NBLK, 256, 0, s0>>>(hb, out);
}